// round 1
// baseline (speedup 1.0000x reference)
#include <cuda_runtime.h>

#define HWSZ (512*512)

__device__ __forceinline__ float ex2f(float x) {
    float r; asm("ex2.approx.f32 %0, %1;" : "=f"(r) : "f"(x)); return r;
}
__device__ __forceinline__ float rcpf(float x) {
    float r; asm("rcp.approx.f32 %0, %1;" : "=f"(r) : "f"(x)); return r;
}

__global__ __launch_bounds__(256) void GaussPSF_kernel(
    const float* __restrict__ img,
    const float* __restrict__ psf,
    float* __restrict__ out)
{
    // Shared tile: (c0,c1,c2,q) per halo pixel, q = -log2e / (2*w^2 + eps)
    __shared__ float4 tile[42 * 42];

    const int tx = threadIdx.x;           // 0..31
    const int ty = threadIdx.y;           // 0..7
    const int tid = ty * 32 + tx;
    const int x0 = blockIdx.x * 32;
    const int y0 = blockIdx.y * 32;
    const int b  = blockIdx.z;

    const float* imb = img + (size_t)b * 3 * HWSZ;
    const float* psb = psf + (size_t)b * HWSZ;

    // ---- stage halo tile ----
    for (int i = tid; i < 42 * 42; i += 256) {
        int sy = i / 42;
        int sx = i - sy * 42;
        int gy = y0 - 5 + sy;
        int gx = x0 - 5 + sx;
        float4 r;
        if ((unsigned)gy < 512u && (unsigned)gx < 512u) {
            int p = gy * 512 + gx;
            r.x = imb[p];
            r.y = imb[HWSZ + p];
            r.z = imb[2 * HWSZ + p];
            float w = psb[p];
            float t = fmaf(w + w, w, 1e-5f);        // 2w^2 + eps
            r.w = -1.4426950408889634f * rcpf(t);   // q (negative)
        } else {
            r.x = 0.f; r.y = 0.f; r.z = 0.f;
            r.w = -1e30f;                            // exp2(d2*q) -> 0 (mask)
        }
        tile[i] = r;
    }
    __syncthreads();

    // ---- 4 outputs per thread, rows y0 + ty*4 + (0..3), column x0 + tx ----
    unsigned long long a01[4], a2w[4];   // f32x2 accumulators: (out0,out1), (out2,wsum)
    #pragma unroll
    for (int o = 0; o < 4; ++o) { a01[o] = 0ull; a2w[o] = 0ull; }

    const int rowbase = ty * 4;

    #pragma unroll
    for (int s = 0; s < 14; ++s) {            // site rows relative: shared row = rowbase + s
        #pragma unroll
        for (int j = 0; j < 11; ++j) {        // site cols: shared col = tx + j
            float4 r = tile[(rowbase + s) * 42 + tx + j];
            unsigned long long c01, c2w;
            asm("mov.b64 %0, {%1,%2};" : "=l"(c01) : "f"(r.x), "f"(r.y));
            asm("mov.b64 %0, {%1,%2};" : "=l"(c2w) : "f"(r.z), "f"(1.0f));
            #pragma unroll
            for (int o = 0; o < 4; ++o) {
                const int dy = s - 5 - o;     // compile-time after unroll
                if (dy >= -5 && dy <= 5) {
                    const float d2 = (float)(dy * dy + (j - 5) * (j - 5));
                    float k = ex2f(d2 * r.w);
                    unsigned long long k2;
                    asm("mov.b64 %0, {%1,%2};" : "=l"(k2) : "f"(k), "f"(k));
                    asm("fma.rn.f32x2 %0, %1, %2, %3;"
                        : "=l"(a01[o]) : "l"(c01), "l"(k2), "l"(a01[o]));
                    asm("fma.rn.f32x2 %0, %1, %2, %3;"
                        : "=l"(a2w[o]) : "l"(c2w), "l"(k2), "l"(a2w[o]));
                }
            }
        }
    }

    // ---- normalize & write ----
    float* ob = out + (size_t)b * 3 * HWSZ;
    #pragma unroll
    for (int o = 0; o < 4; ++o) {
        float o0, o1, o2, ws;
        asm("mov.b64 {%0,%1}, %2;" : "=f"(o0), "=f"(o1) : "l"(a01[o]));
        asm("mov.b64 {%0,%1}, %2;" : "=f"(o2), "=f"(ws) : "l"(a2w[o]));
        float rw = rcpf(ws);
        int y = y0 + rowbase + o;
        int p = y * 512 + x0 + tx;
        ob[p]            = o0 * rw;
        ob[HWSZ + p]     = o1 * rw;
        ob[2 * HWSZ + p] = o2 * rw;
    }
}

extern "C" void kernel_launch(void* const* d_in, const int* in_sizes, int n_in,
                              void* d_out, int out_size)
{
    const float* img = (const float*)d_in[0];   // (4,3,512,512) f32
    const float* psf = (const float*)d_in[1];   // (4,512,512)   f32
    float* out = (float*)d_out;                 // (4,3,512,512) f32

    dim3 block(32, 8, 1);
    dim3 grid(512 / 32, 512 / 32, 4);
    GaussPSF_kernel<<<grid, block>>>(img, psf, out);
}

// round 2
// speedup vs baseline: 1.0082x; 1.0082x over previous
#include <cuda_runtime.h>

#define HWSZ (512*512)
typedef unsigned long long u64;

__device__ __forceinline__ float ex2f(float x) {
    float r; asm("ex2.approx.f32 %0, %1;" : "=f"(r) : "f"(x)); return r;
}
__device__ __forceinline__ float rcpf(float x) {
    float r; asm("rcp.approx.f32 %0, %1;" : "=f"(r) : "f"(x)); return r;
}
__device__ __forceinline__ u64 pk(float a, float b) {
    u64 r; asm("mov.b64 %0, {%1,%2};" : "=l"(r) : "f"(a), "f"(b)); return r;
}
__device__ __forceinline__ u64 mul2(u64 a, u64 b) {
    u64 r; asm("mul.rn.f32x2 %0, %1, %2;" : "=l"(r) : "l"(a), "l"(b)); return r;
}
__device__ __forceinline__ u64 fma2(u64 a, u64 b, u64 c) {
    u64 r; asm("fma.rn.f32x2 %0, %1, %2, %3;" : "=l"(r) : "l"(a), "l"(b), "l"(c)); return r;
}
__device__ __forceinline__ u64 add2(u64 a, u64 b) {
    u64 r; asm("add.rn.f32x2 %0, %1, %2;" : "=l"(r) : "l"(a), "l"(b)); return r;
}

__global__ __launch_bounds__(128) void GaussPSF_kernel(
    const float* __restrict__ img,
    const float* __restrict__ psf,
    float* __restrict__ out)
{
    // Shared tile: (c0,c1,c2,q) per halo pixel, q = -log2e / (2*w^2 + eps)
    __shared__ float4 tile[42 * 42];

    const int tx = threadIdx.x;           // 0..31
    const int ty = threadIdx.y;           // 0..3
    const int tid = ty * 32 + tx;
    const int x0 = blockIdx.x * 32;
    const int y0 = blockIdx.y * 32;
    const int b  = blockIdx.z;

    const float* imb = img + (size_t)b * 3 * HWSZ;
    const float* psb = psf + (size_t)b * HWSZ;

    // ---- stage halo tile ----
    for (int i = tid; i < 42 * 42; i += 128) {
        int sy = i / 42;
        int sx = i - sy * 42;
        int gy = y0 - 5 + sy;
        int gx = x0 - 5 + sx;
        float4 r;
        if ((unsigned)gy < 512u && (unsigned)gx < 512u) {
            int p = gy * 512 + gx;
            r.x = imb[p];
            r.y = imb[HWSZ + p];
            r.z = imb[2 * HWSZ + p];
            float w = psb[p];
            float t = fmaf(w + w, w, 1e-5f);        // 2w^2 + eps
            r.w = -1.4426950408889634f * rcpf(t);   // q (negative)
        } else {
            r.x = 0.f; r.y = 0.f; r.z = 0.f;
            r.w = -1e30f;                            // u = exp2(q) -> 0 (mask)
        }
        tile[i] = r;
    }
    __syncthreads();

    // ---- 8 outputs per thread: rows y0 + ty*8 + (0..7), column x0 + tx ----
    u64 a01[8], a2w[8];   // f32x2 accumulators: (out0,out1), (out2,wsum)
    #pragma unroll
    for (int o = 0; o < 8; ++o) { a01[o] = 0ull; a2w[o] = 0ull; }

    const int rowbase = ty * 8;

    #pragma unroll
    for (int s = 0; s < 18; ++s) {            // shared row = rowbase + s
        #pragma unroll
        for (int j = 0; j < 11; ++j) {        // shared col = tx + j
            float4 r = tile[(rowbase + s) * 42 + tx + j];

            // u = exp2(q); integer-power chain done in f32x2 pairs
            float u = ex2f(r.w);
            u64 p1  = pk(u, u);               // u^1
            u64 t2  = mul2(p1, p1);           // u^2
            u64 q4  = mul2(t2, t2);           // u^4
            u64 t8  = mul2(q4, q4);           // u^8
            u64 q9  = mul2(t8, p1);           // u^9
            u64 q16 = mul2(t8, t8);           // u^16
            u64 q25 = mul2(q16, q9);          // u^25

            u64 P[6];
            P[1] = p1; P[2] = q4; P[3] = q9; P[4] = q16; P[5] = q25;

            // premultiply channels by u^{dx^2} (dx fixed per j)
            const int dxa = (j < 5) ? (5 - j) : (j - 5);
            u64 c01 = pk(r.x, r.y);
            u64 c2w = pk(r.z, 1.0f);
            if (dxa != 0) {
                c01 = mul2(c01, P[dxa]);
                c2w = mul2(c2w, P[dxa]);
            }

            #pragma unroll
            for (int o = 0; o < 8; ++o) {
                const int dy  = s - 5 - o;     // compile-time after unroll
                const int dya = (dy < 0) ? -dy : dy;
                if (dya <= 5) {
                    if (dya == 0) {
                        a01[o] = add2(a01[o], c01);
                        a2w[o] = add2(a2w[o], c2w);
                    } else {
                        a01[o] = fma2(c01, P[dya], a01[o]);
                        a2w[o] = fma2(c2w, P[dya], a2w[o]);
                    }
                }
            }
        }
    }

    // ---- normalize & write ----
    float* ob = out + (size_t)b * 3 * HWSZ;
    #pragma unroll
    for (int o = 0; o < 8; ++o) {
        float o0, o1, o2, ws;
        asm("mov.b64 {%0,%1}, %2;" : "=f"(o0), "=f"(o1) : "l"(a01[o]));
        asm("mov.b64 {%0,%1}, %2;" : "=f"(o2), "=f"(ws) : "l"(a2w[o]));
        float rw = rcpf(ws);
        int y = y0 + rowbase + o;
        int p = y * 512 + x0 + tx;
        ob[p]            = o0 * rw;
        ob[HWSZ + p]     = o1 * rw;
        ob[2 * HWSZ + p] = o2 * rw;
    }
}

extern "C" void kernel_launch(void* const* d_in, const int* in_sizes, int n_in,
                              void* d_out, int out_size)
{
    const float* img = (const float*)d_in[0];   // (4,3,512,512) f32
    const float* psf = (const float*)d_in[1];   // (4,512,512)   f32
    float* out = (float*)d_out;                 // (4,3,512,512) f32

    dim3 block(32, 4, 1);
    dim3 grid(512 / 32, 512 / 32, 4);
    GaussPSF_kernel<<<grid, block>>>(img, psf, out);
}

// round 3
// speedup vs baseline: 1.0837x; 1.0749x over previous
#include <cuda_runtime.h>

#define HWSZ (512*512)
typedef unsigned long long u64;

__device__ __forceinline__ float ex2f(float x) {
    float r; asm("ex2.approx.f32 %0, %1;" : "=f"(r) : "f"(x)); return r;
}
__device__ __forceinline__ float rcpf(float x) {
    float r; asm("rcp.approx.f32 %0, %1;" : "=f"(r) : "f"(x)); return r;
}
__device__ __forceinline__ u64 pk(float a, float b) {
    u64 r; asm("mov.b64 %0, {%1,%2};" : "=l"(r) : "f"(a), "f"(b)); return r;
}
__device__ __forceinline__ u64 mul2(u64 a, u64 b) {
    u64 r; asm("mul.rn.f32x2 %0, %1, %2;" : "=l"(r) : "l"(a), "l"(b)); return r;
}
__device__ __forceinline__ u64 fma2(u64 a, u64 b, u64 c) {
    u64 r; asm("fma.rn.f32x2 %0, %1, %2, %3;" : "=l"(r) : "l"(a), "l"(b), "l"(c)); return r;
}
__device__ __forceinline__ u64 add2(u64 a, u64 b) {
    u64 r; asm("add.rn.f32x2 %0, %1, %2;" : "=l"(r) : "l"(a), "l"(b)); return r;
}

__global__ __launch_bounds__(128, 8) void GaussPSF_kernel(
    const float* __restrict__ img,
    const float* __restrict__ psf,
    float* __restrict__ out)
{
    // Shared tile: (c0,c1,c2,u) per halo pixel, u = exp2(-log2e/(2*w^2+eps))
    __shared__ float4 tile[42 * 42];

    const int tx = threadIdx.x;           // 0..31
    const int ty = threadIdx.y;           // 0..3
    const int tid = ty * 32 + tx;
    const int x0 = blockIdx.x * 32;
    const int y0 = blockIdx.y * 32;
    const int b  = blockIdx.z;

    const float* imb = img + (size_t)b * 3 * HWSZ;
    const float* psb = psf + (size_t)b * HWSZ;

    // ---- stage halo tile (EX2/RCP done ONCE per site here) ----
    for (int i = tid; i < 42 * 42; i += 128) {
        int sy = i / 42;
        int sx = i - sy * 42;
        int gy = y0 - 5 + sy;
        int gx = x0 - 5 + sx;
        float4 r;
        if ((unsigned)gy < 512u && (unsigned)gx < 512u) {
            int p = gy * 512 + gx;
            r.x = imb[p];
            r.y = imb[HWSZ + p];
            r.z = imb[2 * HWSZ + p];
            float w = psb[p];
            float t = fmaf(w + w, w, 1e-5f);                     // 2w^2 + eps
            r.w = ex2f(-1.4426950408889634f * rcpf(t));          // u = exp2(q)
        } else {
            r.x = 0.f; r.y = 0.f; r.z = 0.f;
            r.w = 0.f;                                            // u=0 -> all powers 0 (mask)
        }
        tile[i] = r;
    }
    __syncthreads();

    // ---- 8 outputs per thread: rows y0 + ty*8 + (0..7), column x0 + tx ----
    u64 a01[8], a2w[8];   // f32x2 accumulators: (out0,out1), (out2,wsum)
    #pragma unroll
    for (int o = 0; o < 8; ++o) { a01[o] = 0ull; a2w[o] = 0ull; }

    const int rowbase = ty * 8;

    #pragma unroll
    for (int s = 0; s < 18; ++s) {            // shared row = rowbase + s
        const int base = (rowbase + s) * 42 + tx;
        float4 r = tile[base];                // prefetch j=0
        #pragma unroll
        for (int j = 0; j < 11; ++j) {        // shared col = tx + j
            float4 nxt;
            if (j < 10) nxt = tile[base + j + 1];   // prefetch next site

            // integer-power chain on packed pairs {u,u}
            u64 p1  = pk(r.w, r.w);           // u^1
            u64 t2  = mul2(p1, p1);           // u^2
            u64 q4  = mul2(t2, t2);           // u^4
            u64 t8  = mul2(q4, q4);           // u^8
            u64 q9  = mul2(t8, p1);           // u^9
            u64 q16 = mul2(t8, t8);           // u^16
            u64 q25 = mul2(q16, q9);          // u^25

            u64 P[6];
            P[1] = p1; P[2] = q4; P[3] = q9; P[4] = q16; P[5] = q25;

            // premultiply channels by u^{dx^2} (dx fixed per j)
            const int dxa = (j < 5) ? (5 - j) : (j - 5);
            u64 c01 = pk(r.x, r.y);
            u64 c2w = pk(r.z, 1.0f);
            if (dxa != 0) {
                c01 = mul2(c01, P[dxa]);
                c2w = mul2(c2w, P[dxa]);
            }

            #pragma unroll
            for (int o = 0; o < 8; ++o) {
                const int dy  = s - 5 - o;     // compile-time after unroll
                const int dya = (dy < 0) ? -dy : dy;
                if (dya <= 5) {
                    if (dya == 0) {
                        a01[o] = add2(a01[o], c01);
                        a2w[o] = add2(a2w[o], c2w);
                    } else {
                        a01[o] = fma2(c01, P[dya], a01[o]);
                        a2w[o] = fma2(c2w, P[dya], a2w[o]);
                    }
                }
            }
            r = nxt;
        }
    }

    // ---- normalize & write ----
    float* ob = out + (size_t)b * 3 * HWSZ;
    #pragma unroll
    for (int o = 0; o < 8; ++o) {
        float o0, o1, o2, ws;
        asm("mov.b64 {%0,%1}, %2;" : "=f"(o0), "=f"(o1) : "l"(a01[o]));
        asm("mov.b64 {%0,%1}, %2;" : "=f"(o2), "=f"(ws) : "l"(a2w[o]));
        float rw = rcpf(ws);
        int y = y0 + rowbase + o;
        int p = y * 512 + x0 + tx;
        ob[p]            = o0 * rw;
        ob[HWSZ + p]     = o1 * rw;
        ob[2 * HWSZ + p] = o2 * rw;
    }
}

extern "C" void kernel_launch(void* const* d_in, const int* in_sizes, int n_in,
                              void* d_out, int out_size)
{
    const float* img = (const float*)d_in[0];   // (4,3,512,512) f32
    const float* psf = (const float*)d_in[1];   // (4,512,512)   f32
    float* out = (float*)d_out;                 // (4,3,512,512) f32

    dim3 block(32, 4, 1);
    dim3 grid(512 / 32, 512 / 32, 4);
    GaussPSF_kernel<<<grid, block>>>(img, psf, out);
}